// round 14
// baseline (speedup 1.0000x reference)
#include <cuda_runtime.h>
#include <cuda_bf16.h>
#include <cstdint>

// ============================================================================
// EqProp relaxation — round 14: persistent sweep kernel.
//   bf16 3-term HMMA core (proven) + ONE kernel for all 25 sweeps with
//   software grid barriers (128 co-resident CTAs; 1 tile/CTA/phase).
//   L1-coherence: mutable state flows via cp.async.cg (L2-only) and __ldcg.
// GEMM: D += Ah*Bh + Al*Bh + Ah*Bl  (fp32 accum; A,B split hi/lo bf16)
// ============================================================================

#define BATCHN  1024
#define DHID    2048
#define DOUT    1000
#define DOUTP   1024
#define N_RELAX 25
#define LR      0.3f

#define LDS_B   80                  // (32+8) bf16 per SMEM row
#define MAT_A_B (128 * LDS_B)       // 10240 B per 128-row matrix tile
#define NCTAS   128

__device__ __forceinline__ uint32_t smem_u32(const void* p) {
    uint32_t a;
    asm("{ .reg .u64 t; cvta.to.shared.u64 t, %1; cvt.u32.u64 %0, t; }" : "=r"(a) : "l"(p));
    return a;
}

#define CP16(dst, src) asm volatile("cp.async.cg.shared.global [%0], [%1], 16;" :: "r"(dst), "l"(src) : "memory")
#define CP_COMMIT()    asm volatile("cp.async.commit_group;" ::: "memory")
#define CP_WAIT0()     asm volatile("cp.async.wait_group 0;" ::: "memory")

#define LDSM4(r, a) \
    asm volatile("ldmatrix.sync.aligned.m8n8.x4.shared.b16 {%0,%1,%2,%3}, [%4];" \
                 : "=r"((r)[0]), "=r"((r)[1]), "=r"((r)[2]), "=r"((r)[3]) : "r"(a))

#define MMA16816(c, a, b0, b1) \
    asm volatile("mma.sync.aligned.m16n8k16.row.col.f32.bf16.bf16.f32 " \
                 "{%0,%1,%2,%3},{%4,%5,%6,%7},{%8,%9},{%0,%1,%2,%3};" \
                 : "+f"((c)[0]), "+f"((c)[1]), "+f"((c)[2]), "+f"((c)[3]) \
                 : "r"((a)[0]), "r"((a)[1]), "r"((a)[2]), "r"((a)[3]), "r"(b0), "r"(b1))

// --- static device storage ---------------------------------------------------
#define MEL 1048576
__device__ __nv_bfloat16 g_bf[70u * MEL];
__device__ float g_f[8u * MEL + 1024u * 1000u];
__device__ unsigned g_bar_count = 0;
__device__ unsigned g_bar_gen = 0;

#define OFF_XH   (0u)
#define OFF_XL   (2u*MEL)
#define OFF_RXH  (4u*MEL)
#define OFF_RXL  (6u*MEL)
#define OFF_S1H  (8u*MEL)
#define OFF_S1L  (10u*MEL)
#define OFF_S2H  (12u*MEL)
#define OFF_S2L  (14u*MEL)
#define OFF_S3H  (16u*MEL)
#define OFF_S3L  (18u*MEL)
#define OFF_S4H  (20u*MEL)
#define OFF_S4L  (21u*MEL)
#define OFF_WT0H (22u*MEL)
#define OFF_WT0L (26u*MEL)
#define OFF_WT1H (30u*MEL)
#define OFF_WT1L (34u*MEL)
#define OFF_WT2H (38u*MEL)
#define OFF_WT2L (42u*MEL)
#define OFF_WT3H (46u*MEL)
#define OFF_WT3L (48u*MEL)
#define OFF_W1H  (50u*MEL)
#define OFF_W1L  (54u*MEL)
#define OFF_W2H  (58u*MEL)
#define OFF_W2L  (62u*MEL)
#define OFF_W3H  (66u*MEL)
#define OFF_W3L  (68u*MEL)
#define OFF_S1F  (0u)
#define OFF_S2F  (2u*MEL)
#define OFF_S3F  (4u*MEL)
#define OFF_CXF  (6u*MEL)
#define OFF_S4F  (8u*MEL)

// --- conversion kernels ------------------------------------------------------
__device__ __forceinline__ void split2(float v, __nv_bfloat16& h, __nv_bfloat16& l) {
    h = __float2bfloat16(v);
    l = __float2bfloat16(v - __bfloat162float(h));
}

__global__ void convert_x_kernel(const float* __restrict__ x,
                                 __nv_bfloat16* xh, __nv_bfloat16* xl,
                                 __nv_bfloat16* rxh, __nv_bfloat16* rxl, int n) {
    int i = blockIdx.x * blockDim.x + threadIdx.x;
    if (i < n) {
        float v = x[i];
        __nv_bfloat16 h, l;
        split2(v, h, l); xh[i] = h; xl[i] = l;
        float c = fminf(fmaxf(v, 0.0f), 1.0f);
        split2(c, h, l); rxh[i] = h; rxl[i] = l;
    }
}

__global__ void convert_w_kernel(const float* __restrict__ W, int R, int C, int Cpad,
                                 __nv_bfloat16* oh, __nv_bfloat16* ol) {
    int i = blockIdx.x * blockDim.x + threadIdx.x;
    if (i < R * Cpad) {
        int r = i / Cpad, c = i - r * Cpad;
        float v = (c < C) ? W[(size_t)r * C + c] : 0.0f;
        __nv_bfloat16 h, l;
        split2(v, h, l); oh[i] = h; ol[i] = l;
    }
}

__global__ void transpose_w_kernel(const float* __restrict__ W, int R, int C, int Cpad,
                                   __nv_bfloat16* oh, __nv_bfloat16* ol) {
    __shared__ float t[32][33];
    int r0 = blockIdx.x * 32;
    int c0 = blockIdx.y * 32;
    int tx = threadIdx.x, ty = threadIdx.y;
#pragma unroll
    for (int i = 0; i < 4; i++) {
        int r = r0 + ty + i * 8, c = c0 + tx;
        t[ty + i * 8][tx] = (c < C) ? W[(size_t)r * C + c] : 0.0f;
    }
    __syncthreads();
#pragma unroll
    for (int i = 0; i < 4; i++) {
        int c = c0 + ty + i * 8;
        int r = r0 + tx;
        if (c < Cpad) {
            float v = t[tx][ty + i * 8];
            __nv_bfloat16 h, l;
            split2(v, h, l);
            oh[(size_t)c * R + r] = h;
            ol[(size_t)c * R + r] = l;
        }
    }
}

// --- GEMM core (device function; proven round-3/13 pipeline) -----------------
// mode 0: out = clip(acc + add + bias)
// mode 1: s = __ldcg(Sold); out = clip(s + LR*(bias + acc + add - s))
// mode 3: outf = acc (raw)
template <int BN>
__device__ __forceinline__ void gemm_core(
    char* smem, int bx, int by,
    const __nv_bfloat16* A1h, const __nv_bfloat16* A1l, int K1,
    const __nv_bfloat16* B1h, const __nv_bfloat16* B1l,
    const __nv_bfloat16* A2h, const __nv_bfloat16* A2l, int K2,
    const __nv_bfloat16* B2h, const __nv_bfloat16* B2l,
    const float* bias, const float* Sold, const float* addf,
    float* outf, __nv_bfloat16* outh, __nv_bfloat16* outl,
    int Nreal, int Npad, int mode)
{
    constexpr int WCOLS = BN / 4;
    constexpr int NT    = WCOLS / 8;
    constexpr int NPR   = NT / 2;
    constexpr int MATB  = BN * LDS_B;
    constexpr int OFF_AH = 0;
    constexpr int OFF_AL = MAT_A_B;
    constexpr int OFF_BH = 2 * MAT_A_B;
    constexpr int OFF_BL = 2 * MAT_A_B + MATB;
    constexpr int SS     = 2 * MAT_A_B + 2 * MATB;

    const uint32_t sbase = smem_u32(smem);
    const int tid  = threadIdx.x;
    const int wid  = tid >> 5, lane = tid & 31;
    const int wm   = wid >> 2;
    const int wn   = wid & 3;
    const int m0   = by * 128;
    const int n0   = bx * BN;

    float acc[4][NT][4];
#pragma unroll
    for (int i = 0; i < 4; i++)
#pragma unroll
        for (int j = 0; j < NT; j++)
#pragma unroll
            for (int q = 0; q < 4; q++) acc[i][j][q] = 0.0f;

    const int nch1 = K1 >> 5;
    const int nch2 = K2 >> 5;
    const int nch  = nch1 + nch2;

    auto issue_loads = [&](int c, int st) {
        const __nv_bfloat16 *pah, *pal, *pbh, *pbl;
        int ld, k0;
        if (c < nch1) { pah = A1h; pal = A1l; pbh = B1h; pbl = B1l; ld = K1; k0 = c << 5; }
        else          { pah = A2h; pal = A2l; pbh = B2h; pbl = B2l; ld = K2; k0 = (c - nch1) << 5; }
        const uint32_t stb = sbase + st * SS;
#pragma unroll
        for (int j = 0; j < 2; j++) {
            int v = (tid << 1) | j;
            int r = v >> 2, q = v & 3;
            uint32_t soff = (uint32_t)(r * LDS_B + q * 16);
            size_t goff = (size_t)(m0 + r) * ld + k0 + q * 8;
            CP16(stb + OFF_AH + soff, pah + goff);
            CP16(stb + OFF_AL + soff, pal + goff);
        }
#pragma unroll
        for (int v = tid; v < BN * 4; v += 256) {
            int r = v >> 2, q = v & 3;
            uint32_t soff = (uint32_t)(r * LDS_B + q * 16);
            size_t goff = (size_t)(n0 + r) * ld + k0 + q * 8;
            CP16(stb + OFF_BH + soff, pbh + goff);
            CP16(stb + OFF_BL + soff, pbl + goff);
        }
    };

    const int lt = lane >> 3;
    const int lr = lane & 7;
    const uint32_t a_lane_off = (uint32_t)((wm * 64 + (lt & 1) * 8 + lr) * LDS_B + (lt >> 1) * 16);
    const uint32_t b_lane_off = (uint32_t)((wn * WCOLS + (lt >> 1) * 8 + lr) * LDS_B + (lt & 1) * 16);

    issue_loads(0, 0);
    CP_COMMIT();

    for (int i = 0; i < nch; i++) {
        CP_WAIT0();
        __syncthreads();
        if (i + 1 < nch) { issue_loads(i + 1, (i + 1) & 1); CP_COMMIT(); }

        const uint32_t stb = sbase + (i & 1) * SS;
        const uint32_t sAh = stb + OFF_AH + a_lane_off;
        const uint32_t sAl = stb + OFF_AL + a_lane_off;
        const uint32_t sBh = stb + OFF_BH + b_lane_off;
        const uint32_t sBl = stb + OFF_BL + b_lane_off;

#pragma unroll
        for (int k16 = 0; k16 < 2; k16++) {
            const uint32_t kb = k16 * 32;
            uint32_t ah[4][4], al[4][4];
#pragma unroll
            for (int mt = 0; mt < 4; mt++) {
                LDSM4(ah[mt], sAh + mt * (16 * LDS_B) + kb);
                LDSM4(al[mt], sAl + mt * (16 * LDS_B) + kb);
            }
            uint32_t bh[NPR][4], bl[NPR][4];
#pragma unroll
            for (int pr = 0; pr < NPR; pr++) {
                LDSM4(bh[pr], sBh + pr * (16 * LDS_B) + kb);
                LDSM4(bl[pr], sBl + pr * (16 * LDS_B) + kb);
            }
#pragma unroll
            for (int mt = 0; mt < 4; mt++) {
#pragma unroll
                for (int nt = 0; nt < NT; nt++) {
                    const int pr = nt >> 1, hx = (nt & 1) * 2;
                    MMA16816(acc[mt][nt], ah[mt], bh[pr][hx], bh[pr][hx + 1]);
                    MMA16816(acc[mt][nt], al[mt], bh[pr][hx], bh[pr][hx + 1]);
                    MMA16816(acc[mt][nt], ah[mt], bl[pr][hx], bl[pr][hx + 1]);
                }
            }
        }
        __syncthreads();
    }

    // ---- epilogue ----
#pragma unroll
    for (int mt = 0; mt < 4; mt++) {
#pragma unroll
        for (int nt = 0; nt < NT; nt++) {
            const int n = n0 + wn * WCOLS + nt * 8 + ((lane & 3) << 1);
#pragma unroll
            for (int half = 0; half < 2; half++) {
                const int m = m0 + wm * 64 + mt * 16 + (lane >> 2) + half * 8;
#pragma unroll
                for (int e = 0; e < 2; e++) {
                    const int nn = n + e;
                    float v = acc[mt][nt][half * 2 + e];
                    if (mode == 3) {
                        if (nn < Nreal) outf[(size_t)m * Nreal + nn] = v;
                        continue;
                    }
                    float r;
                    if (nn < Nreal) {
                        if (addf) v += addf[(size_t)m * Nreal + nn];
                        float bb = bias[nn];
                        if (mode == 0) {
                            r = v + bb;
                        } else {
                            float s = __ldcg(&Sold[(size_t)m * Nreal + nn]);
                            r = s + LR * (bb + v - s);
                        }
                        r = fminf(fmaxf(r, 0.0f), 1.0f);
                        outf[(size_t)m * Nreal + nn] = r;
                    } else {
                        r = 0.0f;
                    }
                    if (nn < Npad) {
                        __nv_bfloat16 h, l;
                        split2(r, h, l);
                        outh[(size_t)m * Npad + nn] = h;
                        outl[(size_t)m * Npad + nn] = l;
                    }
                }
            }
        }
    }
}

// --- standalone GEMM kernel (forward init + cxf cache) -----------------------
template <int BN>
__global__ void __launch_bounds__(256, 1)
eqprop_gemm(const __nv_bfloat16* A1h, const __nv_bfloat16* A1l, int K1,
            const __nv_bfloat16* B1h, const __nv_bfloat16* B1l,
            const float* bias, const float* Sold, const float* addf,
            float* outf, __nv_bfloat16* outh, __nv_bfloat16* outl,
            int Nreal, int Npad, int mode)
{
    extern __shared__ char smem[];
    gemm_core<BN>(smem, blockIdx.x, blockIdx.y,
                  A1h, A1l, K1, B1h, B1l,
                  nullptr, nullptr, 0, nullptr, nullptr,
                  bias, Sold, addf, outf, outh, outl, Nreal, Npad, mode);
}

// --- software grid barrier (all 128 CTAs co-resident) ------------------------
__device__ __forceinline__ void grid_bar() {
    __threadfence();
    __syncthreads();
    if (threadIdx.x == 0) {
        volatile unsigned* gen = &g_bar_gen;
        unsigned g = *gen;
        unsigned t = atomicAdd(&g_bar_count, 1u);
        if (t == NCTAS - 1) {
            g_bar_count = 0;
            __threadfence();
            *gen = g + 1;
        } else {
            while (*gen == g) { }
        }
    }
    __syncthreads();
}

// --- persistent sweep kernel -------------------------------------------------
__global__ void __launch_bounds__(256, 1)
sweep_persistent(
    __nv_bfloat16* rxh, __nv_bfloat16* rxl,
    __nv_bfloat16* s1h, __nv_bfloat16* s1l,
    __nv_bfloat16* s2h, __nv_bfloat16* s2l,
    __nv_bfloat16* s3h, __nv_bfloat16* s3l,
    __nv_bfloat16* s4h, __nv_bfloat16* s4l,
    const __nv_bfloat16* wt1h, const __nv_bfloat16* wt1l,
    const __nv_bfloat16* wt2h, const __nv_bfloat16* wt2l,
    const __nv_bfloat16* wt3h, const __nv_bfloat16* wt3l,
    const __nv_bfloat16* w1h, const __nv_bfloat16* w1l,
    const __nv_bfloat16* w2h, const __nv_bfloat16* w2l,
    const __nv_bfloat16* w3h, const __nv_bfloat16* w3l,
    const float* b1, const float* b2, const float* b3, const float* b4,
    float* s1f, float* s2f, float* s3f, float* s4f,
    const float* cxf, float* dout)
{
    extern __shared__ char smem[];
    const int c  = blockIdx.x;
    const int bx = c & 15;
    const int by = c >> 4;

    for (int it = 0; it < N_RELAX; it++) {
        // l=1: cached rho(x)@W0 (cxf) + s2@W1^T
        gemm_core<128>(smem, bx, by, s2h, s2l, DHID, w1h, w1l,
                       nullptr, nullptr, 0, nullptr, nullptr,
                       b1, s1f, cxf, s1f, s1h, s1l, DHID, DHID, 1);
        grid_bar();
        // l=2: s1@W1 + s3@W2^T
        gemm_core<128>(smem, bx, by, s1h, s1l, DHID, wt1h, wt1l,
                       s3h, s3l, DHID, w2h, w2l,
                       b2, s2f, nullptr, s2f, s2h, s2l, DHID, DHID, 1);
        grid_bar();
        // l=3: s2@W2 + s4@W3^T (K2 padded to 1024; s4 pad cols are zero)
        gemm_core<128>(smem, bx, by, s2h, s2l, DHID, wt2h, wt2l,
                       s4h, s4l, DOUTP, w3h, w3l,
                       b3, s3f, nullptr, s3f, s3h, s3l, DHID, DHID, 1);
        grid_bar();
        // l=4: s3@W3 (BN=64 -> 16x8 = 128 tiles)
        float* out4 = (it == N_RELAX - 1) ? dout : s4f;
        gemm_core<64>(smem, bx, by, s3h, s3l, DHID, wt3h, wt3l,
                      nullptr, nullptr, 0, nullptr, nullptr,
                      b4, s4f, nullptr, out4, s4h, s4l, DOUT, DOUTP, 1);
        if (it + 1 < N_RELAX) grid_bar();
    }
}

// --- host orchestration ------------------------------------------------------
#define SMEM_128 (2 * (2 * MAT_A_B + 2 * 128 * LDS_B))
#define SMEM_64  (2 * (2 * MAT_A_B + 2 * 64 * LDS_B))

extern "C" void kernel_launch(void* const* d_in, const int* in_sizes, int n_in,
                              void* d_out, int out_size)
{
    const float* x  = (const float*)d_in[0];
    const float* W0 = (const float*)d_in[1];
    const float* W1 = (const float*)d_in[2];
    const float* W2 = (const float*)d_in[3];
    const float* W3 = (const float*)d_in[4];
    const float* b1 = (const float*)d_in[5];
    const float* b2 = (const float*)d_in[6];
    const float* b3 = (const float*)d_in[7];
    const float* b4 = (const float*)d_in[8];

    cudaFuncSetAttribute(eqprop_gemm<128>, cudaFuncAttributeMaxDynamicSharedMemorySize, SMEM_128);
    cudaFuncSetAttribute(eqprop_gemm<64>, cudaFuncAttributeMaxDynamicSharedMemorySize, SMEM_64);
    cudaFuncSetAttribute(sweep_persistent, cudaFuncAttributeMaxDynamicSharedMemorySize, SMEM_128);

    __nv_bfloat16* bf;
    float* fp;
    cudaGetSymbolAddress((void**)&bf, g_bf);
    cudaGetSymbolAddress((void**)&fp, g_f);

    __nv_bfloat16 *xh = bf + OFF_XH,  *xl = bf + OFF_XL;
    __nv_bfloat16 *rxh = bf + OFF_RXH, *rxl = bf + OFF_RXL;
    __nv_bfloat16 *s1h = bf + OFF_S1H, *s1l = bf + OFF_S1L;
    __nv_bfloat16 *s2h = bf + OFF_S2H, *s2l = bf + OFF_S2L;
    __nv_bfloat16 *s3h = bf + OFF_S3H, *s3l = bf + OFF_S3L;
    __nv_bfloat16 *s4h = bf + OFF_S4H, *s4l = bf + OFF_S4L;
    __nv_bfloat16 *wt0h = bf + OFF_WT0H, *wt0l = bf + OFF_WT0L;
    __nv_bfloat16 *wt1h = bf + OFF_WT1H, *wt1l = bf + OFF_WT1L;
    __nv_bfloat16 *wt2h = bf + OFF_WT2H, *wt2l = bf + OFF_WT2L;
    __nv_bfloat16 *wt3h = bf + OFF_WT3H, *wt3l = bf + OFF_WT3L;
    __nv_bfloat16 *w1h = bf + OFF_W1H, *w1l = bf + OFF_W1L;
    __nv_bfloat16 *w2h = bf + OFF_W2H, *w2l = bf + OFF_W2L;
    __nv_bfloat16 *w3h = bf + OFF_W3H, *w3l = bf + OFF_W3L;
    float *s1f = fp + OFF_S1F, *s2f = fp + OFF_S2F, *s3f = fp + OFF_S3F;
    float *cxf = fp + OFF_CXF, *s4f = fp + OFF_S4F;

    {
        int n = BATCHN * DHID;
        convert_x_kernel<<<(n + 255) / 256, 256>>>(x, xh, xl, rxh, rxl, n);
    }
    dim3 tb(32, 8);
    transpose_w_kernel<<<dim3(DHID / 32, DHID / 32),  tb>>>(W0, DHID, DHID, DHID,  wt0h, wt0l);
    transpose_w_kernel<<<dim3(DHID / 32, DHID / 32),  tb>>>(W1, DHID, DHID, DHID,  wt1h, wt1l);
    transpose_w_kernel<<<dim3(DHID / 32, DHID / 32),  tb>>>(W2, DHID, DHID, DHID,  wt2h, wt2l);
    transpose_w_kernel<<<dim3(DHID / 32, DOUTP / 32), tb>>>(W3, DHID, DOUT, DOUTP, wt3h, wt3l);
    {
        int n = DHID * DHID;
        convert_w_kernel<<<(n + 255) / 256, 256>>>(W1, DHID, DHID, DHID, w1h, w1l);
        convert_w_kernel<<<(n + 255) / 256, 256>>>(W2, DHID, DHID, DHID, w2h, w2l);
        int n3 = DHID * DOUTP;
        convert_w_kernel<<<(n3 + 255) / 256, 256>>>(W3, DHID, DOUT, DOUTP, w3h, w3l);
    }

    // ---- forward init (layer 1 uses RAW x) ----
    eqprop_gemm<128><<<dim3(16, 8), 256, SMEM_128>>>(xh, xl, DHID, wt0h, wt0l,
        b1, nullptr, nullptr, s1f, s1h, s1l, DHID, DHID, 0);
    eqprop_gemm<128><<<dim3(16, 8), 256, SMEM_128>>>(s1h, s1l, DHID, wt1h, wt1l,
        b2, nullptr, nullptr, s2f, s2h, s2l, DHID, DHID, 0);
    eqprop_gemm<128><<<dim3(16, 8), 256, SMEM_128>>>(s2h, s2l, DHID, wt2h, wt2l,
        b3, nullptr, nullptr, s3f, s3h, s3l, DHID, DHID, 0);
    eqprop_gemm<64><<<dim3(16, 8), 256, SMEM_64>>>(s3h, s3l, DHID, wt3h, wt3l,
        b4, nullptr, nullptr, s4f, s4h, s4l, DOUT, DOUTP, 0);

    // ---- cache loop-invariant rho(x)@W0 (raw fp32 product) ----
    eqprop_gemm<128><<<dim3(16, 8), 256, SMEM_128>>>(rxh, rxl, DHID, wt0h, wt0l,
        b1, nullptr, nullptr, cxf, s1h, s1l, DHID, DHID, 3);

    // ---- all 25 Gauss-Seidel sweeps in ONE persistent kernel ----
    sweep_persistent<<<NCTAS, 256, SMEM_128>>>(
        rxh, rxl, s1h, s1l, s2h, s2l, s3h, s3l, s4h, s4l,
        wt1h, wt1l, wt2h, wt2l, wt3h, wt3l,
        w1h, w1l, w2h, w2l, w3h, w3l,
        b1, b2, b3, b4,
        s1f, s2f, s3f, s4f, cxf, (float*)d_out);
}